// round 4
// baseline (speedup 1.0000x reference)
#include <cuda_runtime.h>

// Fixed problem shape (GNNReachabilityNet): N=100000 nodes, E=1600000 edges, G=64 graphs.
#define NMAX  100352
#define GMAX  64
#define EMAXH 800000   // max edge pairs (E/2)

struct Params {
    float p1[11], q1[11], p2[11], q2[11];
    float ps, qs, s0, t0, b2, bo;
};

__device__ Params   gP;
__device__ float    g_alpha[NMAX];   // alpha = x.p2
__device__ float2   g_bg[NMAX];      // (beta = x.q2, gamma = x.p1)
__device__ float    g_delta[NMAX];   // delta = x.q1
__device__ float2   g_agg[NMAX];     // (sum alpha over incoming, deg)
__device__ float    g_w[NMAX];       // w[u] = beta[u] + s[u]
__device__ float    g_aggs[NMAX];    // sum of w[src] over incoming
__device__ int4     g_eidx[EMAXH];   // packed (s0,d0,s1,d1) per edge pair
__device__ unsigned g_outmax[GMAX];  // order-encoded float max
__device__ unsigned          g_cnt  = 0;  // barrier arrival counter
__device__ volatile unsigned g_gen  = 0;  // barrier generation
__device__ unsigned          g_done = 0;  // final-phase completion counter
__device__ unsigned          g_sink = 0;  // DCE sink for prefetch

__device__ __forceinline__ unsigned enc_f(float f) {
    unsigned u = __float_as_uint(f);
    return (u & 0x80000000u) ? ~u : (u | 0x80000000u);
}
__device__ __forceinline__ float dec_f(unsigned e) {
    return (e & 0x80000000u) ? __uint_as_float(e ^ 0x80000000u) : __uint_as_float(~e);
}
#define ENC_NEG_INF 0x007FFFFFu  // enc(-inf)

// Sense-reversing grid barrier. Safe because the host sizes the grid from
// cudaOccupancyMaxActiveBlocksPerMultiprocessor => all blocks co-resident.
__device__ __forceinline__ void grid_bar(unsigned nb) {
    __syncthreads();
    if (threadIdx.x == 0) {
        __threadfence();
        unsigned gen = g_gen;
        if (atomicAdd(&g_cnt, 1u) == nb - 1u) {
            g_cnt = 0u;
            __threadfence();
            g_gen = gen + 1u;
        } else {
            while (g_gen == gen) __nanosleep(64);
        }
        __threadfence();
    }
    __syncthreads();
}

__global__ void __launch_bounds__(256) k_main(
    const float* __restrict__ x, const void* __restrict__ ei,
    const void* __restrict__ batch,
    const float* Wv,  const float* bv,
    const float* We1, const float* be1,
    const float* Wx,  const float* bx,
    const float* We2, const float* be2,
    const float* Wo,  const float* bo,
    float* out, int n, int E, int npair, int out_n)
{
    __shared__ union {
        struct {
            float M1[11 * 128], M2[11 * 128];
            float A1[11 * 64],  A2[11 * 64];
            float c1[128], c2[64], wev[64], wfv[64];
        } f;                                  // fold scratch (block 0 only)
        float sx[256 * 11];                   // x tile for dots phase
    } sh;
    __shared__ float sp2[11], sq2[11], sp1[11], sq1[11];
    __shared__ unsigned smax[GMAX];
    __shared__ int s_flag, s_done;

    const int tid = threadIdx.x, bid = blockIdx.x, nb = gridDim.x;
    const int gthreads = nb * 256;

    // ---- dtype detect (every block, cheap): int64 little-endian nonneg
    // values < 2^31 have all odd 32-bit words zero.
    if (tid == 0) {
        const unsigned* w = (const unsigned*)ei;
        int nz = 0;
#pragma unroll
        for (int i = 0; i < 64; i++) nz += (w[2 * i + 1] != 0u);
        s_flag = (nz == 0);
    }
    __syncthreads();
    const bool f64 = (s_flag != 0);

    // =========================== Phase 0 ===================================
    if (bid == 0) {
        // -- init --
        if (tid < GMAX) g_outmax[tid] = ENC_NEG_INF;
        if (tid == 0) g_done = 0u;
        // -- weight fold (fp32; rel_err margin ~2000x) --
        for (int idx = tid; idx < 11 * 128; idx += 256) {
            int i = idx / 128, m = idx % 128;
            float a1 = 0.f, a2 = 0.f;
            for (int k = 0; k < 64; k++) {
                float wk = Wv[i * 64 + k];
                a1 += wk * We1[k * 128 + m];
                a2 += wk * We1[(64 + k) * 128 + m];
            }
            if (i == 9)  { a1 += We1[128 * 128 + m]; a2 += We1[130 * 128 + m]; }
            if (i == 10) { a1 += We1[129 * 128 + m]; a2 += We1[131 * 128 + m]; }
            sh.f.M1[idx] = a1; sh.f.M2[idx] = a2;
        }
        for (int m = tid; m < 128; m += 256) {
            float c = be1[m];
            for (int k = 0; k < 64; k++)
                c += bv[k] * (We1[k * 128 + m] + We1[(64 + k) * 128 + m]);
            sh.f.c1[m] = c;
        }
        for (int j = tid; j < 64; j += 256) {
            float a = 0.f, b = 0.f;
            for (int o = 0; o < 64; o++) {
                a += We2[j * 64 + o]        * Wo[o];
                b += We2[(64 + j) * 64 + o] * Wo[o];
            }
            sh.f.wev[j] = a; sh.f.wfv[j] = b;
        }
        __syncthreads();
        for (int idx = tid; idx < 11 * 64; idx += 256) {
            int i = idx / 64, o = idx % 64;
            float a1 = 0.f, a2 = 0.f;
            for (int m = 0; m < 128; m++) {
                float wx = Wx[m * 64 + o];
                a1 += sh.f.M1[i * 128 + m] * wx;
                a2 += sh.f.M2[i * 128 + m] * wx;
            }
            sh.f.A1[idx] = a1; sh.f.A2[idx] = a2;
        }
        for (int o = tid; o < 64; o += 256) {
            float c = bx[o];
            for (int m = 0; m < 128; m++) c += sh.f.c1[m] * Wx[m * 64 + o];
            sh.f.c2[o] = c;
        }
        __syncthreads();
        if (tid < 11) {
            int i = tid;
            float a = 0.f, b = 0.f, g = 0.f, d = 0.f;
            for (int o = 0; o < 64; o++) {
                a += sh.f.A2[i * 64 + o] * sh.f.wfv[o]; // p2 -> alpha
                b += sh.f.A2[i * 64 + o] * sh.f.wev[o]; // q2 -> beta
                g += sh.f.A1[i * 64 + o] * sh.f.wfv[o]; // p1 -> gamma
                d += sh.f.A1[i * 64 + o] * sh.f.wev[o]; // q1 -> delta
            }
            gP.p2[i] = a; gP.q2[i] = b; gP.p1[i] = g; gP.q1[i] = d;
        }
        if (tid == 32) {
            float ps = 0.f, qs = 0.f, s0 = 0.f, t0 = 0.f, b2 = 0.f;
            for (int o = 0; o < 64; o++) {
                ps += sh.f.c2[o] * sh.f.wfv[o];
                qs += sh.f.c2[o] * sh.f.wev[o];
                s0 += bx[o]      * sh.f.wfv[o];
                t0 += bx[o]      * sh.f.wev[o];
                b2 += be2[o]     * Wo[o];
            }
            gP.ps = ps; gP.qs = qs; gP.s0 = s0; gP.t0 = t0;
            gP.b2 = b2 + bo[0]; gP.bo = bo[0];
        }
    } else {
        // -- other blocks: warm L2 with edge_index while block 0 folds --
        size_t bytes = (size_t)E * 2u * (f64 ? 8u : 4u);
        size_t n16 = bytes / 16u;
        const uint4* p = (const uint4*)ei;
        unsigned acc = 0;
        for (size_t j = (size_t)(bid - 1) * 256u + tid; j < n16;
             j += (size_t)(nb - 1) * 256u) {
            uint4 v = __ldcg(p + j);
            acc ^= v.x ^ v.y ^ v.z ^ v.w;
        }
        if (acc == 0x9E3779B9u) atomicAdd(&g_sink, 1u);  // keep loads alive
    }
    grid_bar(nb);

    // =========================== Phase 1: dots + zero ======================
    if (tid < 11) {
        sp2[tid] = gP.p2[tid]; sq2[tid] = gP.q2[tid];
        sp1[tid] = gP.p1[tid]; sq1[tid] = gP.q1[tid];
    }
    int ntiles = (n + 255) >> 8;
    for (int tile = bid; tile < ntiles; tile += nb) {
        int base = tile * 2816;
        int lim = n * 11 - base;               // valid floats in this tile
        __syncthreads();                       // sx reuse + sp* visibility
        if (lim >= 2816) {
            const float4* xv = (const float4*)(x + base);
            float4* s4 = (float4*)sh.sx;
            s4[tid]       = xv[tid];
            s4[tid + 256] = xv[tid + 256];
            if (tid + 512 < 704) s4[tid + 512] = xv[tid + 512];
        } else {
            for (int j = tid; j < 2816; j += 256)
                sh.sx[j] = (j < lim) ? x[base + j] : 0.f;
        }
        __syncthreads();
        int v = tile * 256 + tid;
        if (v < n) {
            float a = 0.f, b = 0.f, g = 0.f, d = 0.f;
#pragma unroll
            for (int i = 0; i < 11; i++) {
                float xv = sh.sx[tid * 11 + i];
                a += xv * sp2[i]; b += xv * sq2[i];
                g += xv * sp1[i]; d += xv * sq1[i];
            }
            g_alpha[v] = a;
            g_bg[v]    = make_float2(b, g);
            g_delta[v] = d;
            g_agg[v]   = make_float2(0.f, 0.f);
            g_aggs[v]  = 0.f;
        }
    }
    grid_bar(nb);

    // =========================== Phase 2: edge pass 1 ======================
    const bool evenE = ((E & 1) == 0);
    for (int i = bid * 256 + tid; i < npair; i += gthreads) {
        int e0 = 2 * i;
        int s0, s1, d0, d1;
        bool two = (e0 + 1 < E);
        if (f64) {
            const long long* p = (const long long*)ei;
            if (two) {
                longlong2 sv = *(const longlong2*)(p + e0);
                s0 = (int)sv.x; s1 = (int)sv.y;
                if (evenE) {
                    longlong2 dv = *(const longlong2*)(p + E + e0);
                    d0 = (int)dv.x; d1 = (int)dv.y;
                } else {
                    d0 = (int)p[E + e0]; d1 = (int)p[E + e0 + 1];
                }
            } else {
                s0 = (int)p[e0]; d0 = (int)p[E + e0]; s1 = s0; d1 = -1;
            }
        } else {
            const int* p = (const int*)ei;
            if (two) {
                int2 sv = *(const int2*)(p + e0);
                s0 = sv.x; s1 = sv.y;
                if (evenE) {
                    int2 dv = *(const int2*)(p + E + e0);
                    d0 = dv.x; d1 = dv.y;
                } else {
                    d0 = p[E + e0]; d1 = p[E + e0 + 1];
                }
            } else {
                s0 = p[e0]; d0 = p[E + e0]; s1 = s0; d1 = -1;
            }
        }
        g_eidx[i] = make_int4(s0, d0, s1, d1);

        float a0 = g_alpha[s0];
        if (d1 >= 0) {
            float a1 = g_alpha[s1];
            if (d0 == d1) {
                atomicAdd(&g_agg[d0], make_float2(a0 + a1, 2.f));
            } else {
                atomicAdd(&g_agg[d0], make_float2(a0, 1.f));
                atomicAdd(&g_agg[d1], make_float2(a1, 1.f));
            }
        } else {
            atomicAdd(&g_agg[d0], make_float2(a0, 1.f));
        }
    }
    grid_bar(nb);

    // =========================== Phase 3: nodes ============================
    {
        float ps_ = gP.ps, s0_ = gP.s0;
        for (int v = bid * 256 + tid; v < n; v += gthreads) {
            float2 ag = g_agg[v];
            float2 bg = g_bg[v];
            float s = (ag.y > 0.f) ? (bg.y + (1.f / ag.y) * ag.x + ps_) : s0_;
            g_w[v] = bg.x + s;
        }
    }
    grid_bar(nb);

    // =========================== Phase 4: edge pass 2 ======================
    for (int i = bid * 256 + tid; i < npair; i += gthreads) {
        int4 p = g_eidx[i];
        float w0 = g_w[p.x];
        if (p.w >= 0) {
            float w1 = g_w[p.z];
            if (p.y == p.w) {
                atomicAdd(&g_aggs[p.y], w0 + w1);
            } else {
                atomicAdd(&g_aggs[p.y], w0);
                atomicAdd(&g_aggs[p.w], w1);
            }
        } else {
            atomicAdd(&g_aggs[p.y], w0);
        }
    }
    grid_bar(nb);

    // =========================== Phase 5: final + writeout =================
    if (tid < GMAX) smax[tid] = ENC_NEG_INF;
    __syncthreads();
    {
        float qb = gP.qs + gP.b2, bo_ = gP.bo;
        for (int v = bid * 256 + tid; v < n; v += gthreads) {
            float deg = g_agg[v].y;
            float no = (deg > 0.f) ? (g_delta[v] + qb + (1.f / deg) * g_aggs[v])
                                   : bo_;
            int g = f64 ? (int)((const long long*)batch)[v]
                        : ((const int*)batch)[v];
            atomicMax(&smax[g], enc_f(no));
        }
    }
    __syncthreads();
    if (tid < GMAX && smax[tid] != ENC_NEG_INF)
        atomicMax(&g_outmax[tid], smax[tid]);
    __syncthreads();
    if (tid == 0) {
        __threadfence();
        s_done = (atomicAdd(&g_done, 1u) == (unsigned)nb - 1u);
    }
    __syncthreads();
    if (s_done && tid < GMAX && tid < out_n)
        out[tid] = dec_f(g_outmax[tid]);
}

extern "C" void kernel_launch(void* const* d_in, const int* in_sizes, int n_in,
                              void* d_out, int out_size) {
    const float* x     = (const float*)d_in[0];
    const void*  ei    = d_in[1];
    const void*  batch = d_in[2];
    const float* Wv  = (const float*)d_in[3];
    const float* bv  = (const float*)d_in[4];
    const float* We1 = (const float*)d_in[5];
    const float* be1 = (const float*)d_in[6];
    const float* Wx  = (const float*)d_in[7];
    const float* bx  = (const float*)d_in[8];
    const float* We2 = (const float*)d_in[9];
    const float* be2 = (const float*)d_in[10];
    const float* Wo  = (const float*)d_in[11];
    const float* bo  = (const float*)d_in[12];
    float* out = (float*)d_out;

    int n = in_sizes[0] / 11;   // 100000
    int E = in_sizes[1] / 2;    // 1600000
    if (n > NMAX) n = NMAX;
    if (E > 2 * EMAXH) E = 2 * EMAXH;
    int npair = (E + 1) / 2;

    // Size the persistent grid to guaranteed co-residency (grid barrier safety).
    int sms = 148;
    cudaDeviceGetAttribute(&sms, cudaDevAttrMultiProcessorCount, 0);
    int bpm = 0;
    cudaOccupancyMaxActiveBlocksPerMultiprocessor(&bpm, k_main, 256, 0);
    if (bpm < 1) bpm = 1;
    if (bpm > 4) bpm = 4;
    int grid = sms * bpm;

    k_main<<<grid, 256>>>(x, ei, batch, Wv, bv, We1, be1, Wx, bx,
                          We2, be2, Wo, bo, out, n, E, npair, out_size);
}